// round 5
// baseline (speedup 1.0000x reference)
#include <cuda_runtime.h>
#include <cuda_bf16.h>
#include <cstdint>

#define LL 2048
#define DD 64
#define NBH 32
#define TM 128
#define TN 64
#define NIT (LL/TN)    // 32
#define PSTR 72        // padded row stride in halves (144B: 16B-aligned, ldmatrix conflict-free)

// dynamic smem byte offsets
#define QHI_B 0u
#define QLO_B 18432u
#define KHI_B 36864u
#define KLO_B 46080u
#define VHI_B 55296u
#define VLO_B 64512u
#define PHI_B 73728u
#define PLO_B 92160u
#define RS_B  110592u
#define MB_B  111104u          // valid bitmask, double buffered: 2 x 256 x uint32
#define SM_TOTAL 113152u

__device__ float g_inv[NBH * LL];

__device__ __forceinline__ uint32_t smem_u32(const void* p){
    uint32_t a;
    asm("{ .reg .u64 t; cvta.to.shared.u64 t, %1; cvt.u32.u64 %0, t; }" : "=r"(a) : "l"(p));
    return a;
}
__device__ __forceinline__ void ldsm4(uint32_t* r, uint32_t a){
    asm volatile("ldmatrix.sync.aligned.m8n8.x4.shared.b16 {%0,%1,%2,%3}, [%4];"
        : "=r"(r[0]),"=r"(r[1]),"=r"(r[2]),"=r"(r[3]) : "r"(a));
}
__device__ __forceinline__ void ldsm4t(uint32_t* r, uint32_t a){
    asm volatile("ldmatrix.sync.aligned.m8n8.x4.trans.shared.b16 {%0,%1,%2,%3}, [%4];"
        : "=r"(r[0]),"=r"(r[1]),"=r"(r[2]),"=r"(r[3]) : "r"(a));
}
__device__ __forceinline__ void mma16816(float* c, const uint32_t* a, const uint32_t* b){
    asm volatile("mma.sync.aligned.m16n8k16.row.col.f32.bf16.bf16.f32 "
        "{%0,%1,%2,%3}, {%4,%5,%6,%7}, {%8,%9}, {%0,%1,%2,%3};"
        : "+f"(c[0]),"+f"(c[1]),"+f"(c[2]),"+f"(c[3])
        : "r"(a[0]),"r"(a[1]),"r"(a[2]),"r"(a[3]),"r"(b[0]),"r"(b[1]));
}
__device__ __forceinline__ uint32_t packbf(__nv_bfloat16 a, __nv_bfloat16 b){
    return ((uint32_t)__bfloat16_as_ushort(b)<<16)|(uint32_t)__bfloat16_as_ushort(a);
}
__device__ __forceinline__ void split2(float a, float b, uint32_t& hi, uint32_t& lo){
    __nv_bfloat16 ha=__float2bfloat16(a), hb=__float2bfloat16(b);
    hi = packbf(ha,hb);
    lo = packbf(__float2bfloat16(a-__bfloat162float(ha)),
                __float2bfloat16(b-__bfloat162float(hb)));
}
__device__ __forceinline__ void split_store(char* hi, char* lo, uint32_t off, float4 x){
    uint32_t h0,l0,h1,l1;
    split2(x.x,x.y,h0,l0); split2(x.z,x.w,h1,l1);
    *(uint2*)(hi+off) = make_uint2(h0,h1);
    *(uint2*)(lo+off) = make_uint2(l0,l1);
}

__global__ __launch_bounds__(256,2) void attn_mma(
    const float* __restrict__ q, const float* __restrict__ k,
    const float* __restrict__ v, const int* __restrict__ valid,
    const float* __restrict__ scale_p,
    float* __restrict__ res, float* __restrict__ attw)
{
    extern __shared__ char smem[];
    const uint32_t sb = smem_u32(smem);
    const int tid = threadIdx.x, w = tid>>5, l = tid&31;
    const int wm = w&3, wn = w>>2;        // 4 warps along M, 2 along N
    const int bh = blockIdx.y, q0 = blockIdx.x*TM;
    const float scale = *scale_p;
    float* rowsum = (float*)(smem + RS_B);
    uint32_t* maskbuf = (uint32_t*)(smem + MB_B);   // [2][256]
    if (tid < TM) rowsum[tid] = 0.f;

    // ---- Q load + bf16 hi/lo split ----
    const float4* qsrc = (const float4*)(q + ((size_t)bh*LL+q0)*DD);
    #pragma unroll
    for (int j=0;j<8;j++){
        int i = tid + j*256;
        int row = i>>4, c4 = (i&15)*4;
        split_store(smem+QHI_B, smem+QLO_B, (uint32_t)(row*PSTR+c4)*2u, qsrc[i]);
    }

    const float* kbh_ = k + (size_t)bh*LL*DD;
    const float* vbh_ = v + (size_t)bh*LL*DD;
    const int* validb = valid + ((size_t)bh*LL+q0)*LL;
    float* attwb = attw + ((size_t)bh*LL+q0)*LL;

    // ---- per-lane ldmatrix address bases ----
    const int arow = l&15, acolh = (l>>4)*8;  // A-operand lane mapping
    const int bg = l>>3, blr = l&7;           // B-operand lane mapping
    uint32_t qa[2], pa[2], kbA[2], vbA[2];
    #pragma unroll
    for (int m=0;m<2;m++){
        uint32_t ro = (uint32_t)((wm*32 + m*16 + arow)*PSTR + acolh)*2u;
        qa[m] = sb + QHI_B + ro;
        pa[m] = sb + PHI_B + ro;
    }
    #pragma unroll
    for (int p=0;p<2;p++){
        kbA[p] = sb + KHI_B + (uint32_t)((wn*32 + p*16 + (bg>>1)*8 + blr)*PSTR + (bg&1)*8)*2u;
        vbA[p] = sb + VHI_B + (uint32_t)(((bg&1)*8 + blr)*PSTR + wn*32 + p*16 + (bg>>1)*8)*2u;
    }

    // ---- valid bitmask loader mapping (one uint32 per thread per tile) ----
    const int myrow = tid>>1, myhalf = tid&1;
    const int* vldbase = validb + (size_t)myrow*LL + myhalf*32;

    float ofr[2][4][4];
    #pragma unroll
    for(int m=0;m<2;m++){
        #pragma unroll
        for(int n=0;n<4;n++){
            #pragma unroll
            for(int i=0;i<4;i++) ofr[m][n][i]=0.f;
        }
    }
    float lp[2][2] = {{0.f,0.f},{0.f,0.f}};

    // ---- prologue prefetch: K/V tile 0 into regs, valid tile 0 into maskbuf[0] ----
    const int ldrow = tid>>4, ldc4 = (tid&15)*4;     // this thread's (row,col) in tile loads
    const uint32_t ldoff = (uint32_t)(ldrow*PSTR+ldc4)*2u;
    float4 kreg[4], vreg[4];
    {
        const float4* ks_ = (const float4*)kbh_;
        const float4* vs_ = (const float4*)vbh_;
        #pragma unroll
        for (int j=0;j<4;j++){ kreg[j] = ks_[tid + j*256]; vreg[j] = vs_[tid + j*256]; }
        uint32_t mbits = 0;
        #pragma unroll
        for (int j=0;j<8;j++){
            int4 x = *(const int4*)(vldbase + j*4);
            mbits |= (x.x>0?1u:0u)<<(j*4);
            mbits |= (x.y>0?1u:0u)<<(j*4+1);
            mbits |= (x.z>0?1u:0u)<<(j*4+2);
            mbits |= (x.w>0?1u:0u)<<(j*4+3);
        }
        maskbuf[myrow*2 + myhalf] = mbits;
    }

    #pragma unroll 1
    for (int it=0; it<NIT; ++it){
        const int kb = it*TN;
        const int buf = it & 1;
        __syncthreads();   // prev PV done: K/V/P buffers free; maskbuf[buf] visible
        // ---- store prefetched K,V regs to smem (hi/lo split) ----
        #pragma unroll
        for (int j=0;j<4;j++){
            uint32_t off = ldoff + (uint32_t)(j*16*PSTR)*2u;
            split_store(smem+KHI_B, smem+KLO_B, off, kreg[j]);
            split_store(smem+VHI_B, smem+VLO_B, off, vreg[j]);
        }
        __syncthreads();

        // ---- S = Q K^T, bf16x3 ----
        float sf[2][4][4];
        #pragma unroll
        for(int m=0;m<2;m++){
            #pragma unroll
            for(int n=0;n<4;n++){
                #pragma unroll
                for(int i=0;i<4;i++) sf[m][n][i]=0.f;
            }
        }
        #pragma unroll
        for (int ksI=0; ksI<4; ++ksI){
            uint32_t aH[2][4], aL[2][4], bH[2][4], bL[2][4];
            #pragma unroll
            for (int m=0;m<2;m++){
                ldsm4(aH[m], qa[m] + ksI*32);
                ldsm4(aL[m], qa[m] + (QLO_B-QHI_B) + ksI*32);
            }
            #pragma unroll
            for (int p=0;p<2;p++){
                ldsm4(bH[p], kbA[p] + ksI*32);
                ldsm4(bL[p], kbA[p] + (KLO_B-KHI_B) + ksI*32);
            }
            #pragma unroll
            for (int m=0;m<2;m++){
                #pragma unroll
                for (int n=0;n<4;n++){
                    const uint32_t* bh2 = &bH[n>>1][(n&1)*2];
                    const uint32_t* bl2 = &bL[n>>1][(n&1)*2];
                    mma16816(sf[m][n], aH[m], bh2);
                    mma16816(sf[m][n], aH[m], bl2);
                    mma16816(sf[m][n], aL[m], bh2);
                }
            }
        }

        // ---- prefetch next tile (K/V regs + valid bitmask) — hidden under epilogue+PV ----
        if (it+1 < NIT){
            const float4* ks_ = (const float4*)(kbh_ + (size_t)(kb+TN)*DD);
            const float4* vs_ = (const float4*)(vbh_ + (size_t)(kb+TN)*DD);
            #pragma unroll
            for (int j=0;j<4;j++){ kreg[j] = ks_[tid + j*256]; vreg[j] = vs_[tid + j*256]; }
            uint32_t mbits = 0;
            const int* vp = vldbase + kb + TN;
            #pragma unroll
            for (int j=0;j<8;j++){
                int4 x = *(const int4*)(vp + j*4);
                mbits |= (x.x>0?1u:0u)<<(j*4);
                mbits |= (x.y>0?1u:0u)<<(j*4+1);
                mbits |= (x.z>0?1u:0u)<<(j*4+2);
                mbits |= (x.w>0?1u:0u)<<(j*4+3);
            }
            maskbuf[(1-buf)*256 + myrow*2 + myhalf] = mbits;
        }

        // ---- epilogue: mask (from smem bitmask) + exp + attw store + P split ----
        #pragma unroll
        for (int m=0;m<2;m++){
            const int r0 = wm*32 + m*16 + (l>>2);
            const uint32_t mk0 = maskbuf[buf*256 + r0*2 + wn];
            const uint32_t mk1 = maskbuf[buf*256 + (r0+8)*2 + wn];
            #pragma unroll
            for (int n=0;n<4;n++){
                const int cl = wn*32 + n*8 + (l&3)*2;
                const int sh = n*8 + (l&3)*2;
                float e00 = (mk0>>sh)&1u     ? __expf(sf[m][n][0]*scale) : 0.f;
                float e01 = (mk0>>(sh+1))&1u ? __expf(sf[m][n][1]*scale) : 0.f;
                float e10 = (mk1>>sh)&1u     ? __expf(sf[m][n][2]*scale) : 0.f;
                float e11 = (mk1>>(sh+1))&1u ? __expf(sf[m][n][3]*scale) : 0.f;
                lp[m][0] += e00+e01; lp[m][1] += e10+e11;
                *(float2*)(attwb + (size_t)r0*LL + kb + cl)     = make_float2(e00,e01);
                *(float2*)(attwb + (size_t)(r0+8)*LL + kb + cl) = make_float2(e10,e11);
                uint32_t h_,lo_;
                split2(e00,e01,h_,lo_);
                uint32_t o0 = (uint32_t)(r0*PSTR + cl)*2u;
                *(uint32_t*)(smem+PHI_B+o0) = h_; *(uint32_t*)(smem+PLO_B+o0) = lo_;
                split2(e10,e11,h_,lo_);
                uint32_t o1 = (uint32_t)((r0+8)*PSTR + cl)*2u;
                *(uint32_t*)(smem+PHI_B+o1) = h_; *(uint32_t*)(smem+PLO_B+o1) = lo_;
            }
        }
        __syncthreads();   // P visible to all warps

        // ---- O += P V, bf16x3 (V via ldmatrix.trans) ----
        #pragma unroll
        for (int ksI=0;ksI<4;++ksI){
            uint32_t pH[2][4], pL[2][4], vH[2][4], vL[2][4];
            #pragma unroll
            for (int m=0;m<2;m++){
                ldsm4(pH[m], pa[m] + ksI*32);
                ldsm4(pL[m], pa[m] + (PLO_B-PHI_B) + ksI*32);
            }
            #pragma unroll
            for (int p=0;p<2;p++){
                ldsm4t(vH[p], vbA[p] + ksI*2304);   // 16 key rows * 144B
                ldsm4t(vL[p], vbA[p] + (VLO_B-VHI_B) + ksI*2304);
            }
            #pragma unroll
            for (int m=0;m<2;m++){
                #pragma unroll
                for (int n=0;n<4;n++){
                    const uint32_t* vh2 = &vH[n>>1][(n&1)*2];
                    const uint32_t* vl2 = &vL[n>>1][(n&1)*2];
                    mma16816(ofr[m][n], pH[m], vh2);
                    mma16816(ofr[m][n], pH[m], vl2);
                    mma16816(ofr[m][n], pL[m], vh2);
                }
            }
        }
    }

    // ---- row-sum reduction -> inverse ----
    #pragma unroll
    for (int m=0;m<2;m++){
        #pragma unroll
        for (int h=0;h<2;h++){
            float x = lp[m][h];
            x += __shfl_xor_sync(0xffffffffu, x, 1);
            x += __shfl_xor_sync(0xffffffffu, x, 2);
            if ((l&3)==0) atomicAdd(&rowsum[wm*32 + m*16 + h*8 + (l>>2)], x);
        }
    }
    __syncthreads();
    if (tid < TM){
        float s_ = rowsum[tid];
        float inv = s_>0.f ? 1.f/s_ : 0.f;
        g_inv[bh*LL + q0 + tid] = inv;
        rowsum[tid] = inv;
    }
    __syncthreads();

    // ---- normalized result write ----
    float* resb = res + ((size_t)bh*LL+q0)*DD;
    #pragma unroll
    for (int m=0;m<2;m++){
        const int r0 = wm*32 + m*16 + (l>>2);
        float i0 = rowsum[r0], i1 = rowsum[r0+8];
        #pragma unroll
        for (int n=0;n<4;n++){
            const int dc = wn*32 + n*8 + (l&3)*2;
            *(float2*)(resb + (size_t)r0*DD + dc)     = make_float2(ofr[m][n][0]*i0, ofr[m][n][1]*i0);
            *(float2*)(resb + (size_t)(r0+8)*DD + dc) = make_float2(ofr[m][n][2]*i1, ofr[m][n][3]*i1);
        }
    }
}

// scale att_w rows by 1/l (att_w was written unnormalized)
__global__ __launch_bounds__(256) void fixup_kernel(float* __restrict__ attw)
{
    size_t idx = (size_t)blockIdx.x * blockDim.x + threadIdx.x;   // float4 index
    float inv = g_inv[idx >> 9];
    float4* p = (float4*)attw + idx;
    float4 val = *p;
    val.x *= inv; val.y *= inv; val.z *= inv; val.w *= inv;
    *p = val;
}

extern "C" void kernel_launch(void* const* d_in, const int* in_sizes, int n_in,
                              void* d_out, int out_size)
{
    const float* q     = (const float*)d_in[0];
    const float* k     = (const float*)d_in[1];
    const float* v     = (const float*)d_in[2];
    const int*   valid = (const int*)  d_in[3];
    const float* scale = (const float*)d_in[4];

    float* res  = (float*)d_out;                      // [B,H,L,D]
    float* attw = res + (size_t)NBH * LL * DD;        // [B,H,L,L]

    cudaFuncSetAttribute(attn_mma, cudaFuncAttributeMaxDynamicSharedMemorySize, SM_TOTAL);

    dim3 grid(LL / TM, NBH);   // (16, 32)
    attn_mma<<<grid, 256, SM_TOTAL>>>(q, k, v, valid, scale, res, attw);

    fixup_kernel<<<(NBH * (size_t)LL * LL / 4) / 256, 256>>>(attw);
}

// round 6
// speedup vs baseline: 1.1291x; 1.1291x over previous
#include <cuda_runtime.h>
#include <cuda_bf16.h>
#include <cstdint>

#define LL 2048
#define DD 64
#define NBH 32
#define TM 128
#define TN 64
#define NIT (LL/TN)    // 32
#define PSTR 72        // padded row stride in halves (144B)

// dynamic smem byte offsets
#define QHI_B   0u
#define QLO_B   18432u
#define KV_B    36864u          // two K/V buffers, each 36864B
#define KVSTRIDE 36864u
#define KHI_O   0u              // offsets within a KV buffer
#define KLO_O   9216u
#define VHI_O   18432u
#define VLO_O   27648u
#define RS_B    110592u
#define MB_B    111104u         // valid bitmask, double buffered: 2 x 256 x uint32
#define SM_TOTAL 113152u

__device__ float g_inv[NBH * LL];

__device__ __forceinline__ uint32_t smem_u32(const void* p){
    uint32_t a;
    asm("{ .reg .u64 t; cvta.to.shared.u64 t, %1; cvt.u32.u64 %0, t; }" : "=r"(a) : "l"(p));
    return a;
}
__device__ __forceinline__ void ldsm4(uint32_t* r, uint32_t a){
    asm volatile("ldmatrix.sync.aligned.m8n8.x4.shared.b16 {%0,%1,%2,%3}, [%4];"
        : "=r"(r[0]),"=r"(r[1]),"=r"(r[2]),"=r"(r[3]) : "r"(a));
}
__device__ __forceinline__ void ldsm4t(uint32_t* r, uint32_t a){
    asm volatile("ldmatrix.sync.aligned.m8n8.x4.trans.shared.b16 {%0,%1,%2,%3}, [%4];"
        : "=r"(r[0]),"=r"(r[1]),"=r"(r[2]),"=r"(r[3]) : "r"(a));
}
__device__ __forceinline__ void mma16816(float* c, const uint32_t* a, const uint32_t* b){
    asm volatile("mma.sync.aligned.m16n8k16.row.col.f32.bf16.bf16.f32 "
        "{%0,%1,%2,%3}, {%4,%5,%6,%7}, {%8,%9}, {%0,%1,%2,%3};"
        : "+f"(c[0]),"+f"(c[1]),"+f"(c[2]),"+f"(c[3])
        : "r"(a[0]),"r"(a[1]),"r"(a[2]),"r"(a[3]),"r"(b[0]),"r"(b[1]));
}
__device__ __forceinline__ uint32_t packbf(__nv_bfloat16 a, __nv_bfloat16 b){
    return ((uint32_t)__bfloat16_as_ushort(b)<<16)|(uint32_t)__bfloat16_as_ushort(a);
}
__device__ __forceinline__ void split2(float a, float b, uint32_t& hi, uint32_t& lo){
    __nv_bfloat16 ha=__float2bfloat16(a), hb=__float2bfloat16(b);
    hi = packbf(ha,hb);
    lo = packbf(__float2bfloat16(a-__bfloat162float(ha)),
                __float2bfloat16(b-__bfloat162float(hb)));
}
__device__ __forceinline__ void split_store(char* hi, char* lo, uint32_t off, float4 x){
    uint32_t h0,l0,h1,l1;
    split2(x.x,x.y,h0,l0); split2(x.z,x.w,h1,l1);
    *(uint2*)(hi+off) = make_uint2(h0,h1);
    *(uint2*)(lo+off) = make_uint2(l0,l1);
}

__global__ __launch_bounds__(256,2) void attn_mma(
    const float* __restrict__ q, const float* __restrict__ k,
    const float* __restrict__ v, const int* __restrict__ valid,
    const float* __restrict__ scale_p,
    float* __restrict__ res, float* __restrict__ attw)
{
    extern __shared__ char smem[];
    const uint32_t sb = smem_u32(smem);
    const int tid = threadIdx.x, w = tid>>5, l = tid&31;
    const int bh = blockIdx.y, q0 = blockIdx.x*TM;
    const float scale = *scale_p;
    float* rowsum = (float*)(smem + RS_B);
    uint32_t* maskbuf = (uint32_t*)(smem + MB_B);   // [2][256]
    if (tid < TM) rowsum[tid] = 0.f;

    // ---- Q load + bf16 hi/lo split ----
    const float4* qsrc = (const float4*)(q + ((size_t)bh*LL+q0)*DD);
    #pragma unroll
    for (int j=0;j<8;j++){
        int i = tid + j*256;
        int row = i>>4, c4 = (i&15)*4;
        split_store(smem+QHI_B, smem+QLO_B, (uint32_t)(row*PSTR+c4)*2u, qsrc[i]);
    }

    const float* kbh_ = k + (size_t)bh*LL*DD;
    const float* vbh_ = v + (size_t)bh*LL*DD;
    const int* validb = valid + ((size_t)bh*LL+q0)*LL;
    float* attwb = attw + ((size_t)bh*LL+q0)*LL;

    // ---- per-lane ldmatrix offsets (buffer-relative) ----
    const int bg = l>>3, blr = l&7;
    const uint32_t qa_off = (uint32_t)((w*16 + (l&15))*PSTR + (l>>4)*8)*2u;  // A frag (Q rows)
    uint32_t kb_off[4], vb_off[4];
    #pragma unroll
    for (int p=0;p<4;p++){
        kb_off[p] = (uint32_t)((p*16 + (bg>>1)*8 + blr)*PSTR + (bg&1)*8)*2u;   // K B-frag
        vb_off[p] = (uint32_t)(((bg&1)*8 + blr)*PSTR + p*16 + (bg>>1)*8)*2u;   // V B-frag (trans)
    }

    // ---- K/V tile loader mapping ----
    const int ldrow = tid>>4, ldc4 = (tid&15)*4;
    const uint32_t ldoff = (uint32_t)(ldrow*PSTR+ldc4)*2u;

    // ---- valid bitmask loader mapping ----
    const int myrow = tid>>1, myhalf = tid&1;
    const int* vldbase = validb + (size_t)myrow*LL + myhalf*32;

    float ofr[8][4];
    #pragma unroll
    for(int n=0;n<8;n++){
        #pragma unroll
        for(int i=0;i<4;i++) ofr[n][i]=0.f;
    }
    float lp0 = 0.f, lp1 = 0.f;

    // ---- prologue: K/V tile 0 -> buf0, mask tile 0 -> maskbuf[0] ----
    {
        char* kv0 = smem + KV_B;
        const float4* ks_ = (const float4*)kbh_;
        const float4* vs_ = (const float4*)vbh_;
        #pragma unroll
        for (int j=0;j<4;j++){
            uint32_t off = ldoff + (uint32_t)(j*16*PSTR)*2u;
            split_store(kv0+KHI_O, kv0+KLO_O, off, ks_[tid + j*256]);
            split_store(kv0+VHI_O, kv0+VLO_O, off, vs_[tid + j*256]);
        }
        uint32_t mbits = 0;
        #pragma unroll
        for (int j=0;j<8;j++){
            int4 x = *(const int4*)(vldbase + j*4);
            mbits |= (x.x>0?1u:0u)<<(j*4);
            mbits |= (x.y>0?1u:0u)<<(j*4+1);
            mbits |= (x.z>0?1u:0u)<<(j*4+2);
            mbits |= (x.w>0?1u:0u)<<(j*4+3);
        }
        maskbuf[myrow*2 + myhalf] = mbits;
    }
    __syncthreads();

    const int r0 = w*16 + (l>>2);   // this thread's first S/O row

    #pragma unroll 1
    for (int it=0; it<NIT; ++it){
        const int kb = it*TN;
        const int buf = it & 1;
        const uint32_t kvb = sb + KV_B + (uint32_t)buf*KVSTRIDE;     // current (read)
        char*          kvn = smem + KV_B + (buf^1)*KVSTRIDE;        // next (write)
        const bool have_next = (it+1 < NIT);

        // ---- issue next-K LDG (transient, consumed after S-MMA) ----
        float4 kreg[4];
        if (have_next){
            const float4* ks_ = (const float4*)(kbh_ + (size_t)(kb+TN)*DD);
            #pragma unroll
            for (int j=0;j<4;j++) kreg[j] = ks_[tid + j*256];
        }

        // ---- S = Q K^T, bf16x3 ----
        float sf[8][4];
        #pragma unroll
        for(int n=0;n<8;n++){
            #pragma unroll
            for(int i=0;i<4;i++) sf[n][i]=0.f;
        }
        #pragma unroll
        for (int ksI=0; ksI<4; ++ksI){
            uint32_t aH[4], aL[4];
            ldsm4(aH, sb + QHI_B + qa_off + ksI*32);
            ldsm4(aL, sb + QLO_B + qa_off + ksI*32);
            #pragma unroll
            for (int p=0;p<4;p++){
                uint32_t bH[4], bL[4];
                ldsm4(bH, kvb + KHI_O + kb_off[p] + ksI*32);
                ldsm4(bL, kvb + KLO_O + kb_off[p] + ksI*32);
                #pragma unroll
                for (int nn=0;nn<2;nn++){
                    const int n = p*2+nn;
                    mma16816(sf[n], aH, &bH[nn*2]);
                    mma16816(sf[n], aH, &bL[nn*2]);
                    mma16816(sf[n], aL, &bH[nn*2]);
                }
            }
        }

        // ---- store next-K, issue next-V LDG, prefetch next mask ----
        float4 vreg[4];
        if (have_next){
            #pragma unroll
            for (int j=0;j<4;j++)
                split_store(kvn+KHI_O, kvn+KLO_O, ldoff + (uint32_t)(j*16*PSTR)*2u, kreg[j]);
            const float4* vs_ = (const float4*)(vbh_ + (size_t)(kb+TN)*DD);
            #pragma unroll
            for (int j=0;j<4;j++) vreg[j] = vs_[tid + j*256];
            uint32_t mbits = 0;
            const int* vp = vldbase + kb + TN;
            #pragma unroll
            for (int j=0;j<8;j++){
                int4 x = *(const int4*)(vp + j*4);
                mbits |= (x.x>0?1u:0u)<<(j*4);
                mbits |= (x.y>0?1u:0u)<<(j*4+1);
                mbits |= (x.z>0?1u:0u)<<(j*4+2);
                mbits |= (x.w>0?1u:0u)<<(j*4+3);
            }
            maskbuf[(buf^1)*256 + myrow*2 + myhalf] = mbits;
        }

        // ---- epilogue: mask + exp + attw store + pack P into registers ----
        uint32_t pH[8][2], pL[8][2];
        {
            const uint32_t mk0a = maskbuf[buf*256 + r0*2];
            const uint32_t mk0b = maskbuf[buf*256 + r0*2 + 1];
            const uint32_t mk1a = maskbuf[buf*256 + (r0+8)*2];
            const uint32_t mk1b = maskbuf[buf*256 + (r0+8)*2 + 1];
            #pragma unroll
            for (int n=0;n<8;n++){
                const int cl = n*8 + (l&3)*2;
                const uint32_t mk0 = (n<4)?mk0a:mk0b;
                const uint32_t mk1 = (n<4)?mk1a:mk1b;
                const int sh = cl & 31;
                float e00 = (mk0>>sh)&1u     ? __expf(sf[n][0]*scale) : 0.f;
                float e01 = (mk0>>(sh+1))&1u ? __expf(sf[n][1]*scale) : 0.f;
                float e10 = (mk1>>sh)&1u     ? __expf(sf[n][2]*scale) : 0.f;
                float e11 = (mk1>>(sh+1))&1u ? __expf(sf[n][3]*scale) : 0.f;
                lp0 += e00+e01; lp1 += e10+e11;
                *(float2*)(attwb + (size_t)r0*LL + kb + cl)     = make_float2(e00,e01);
                *(float2*)(attwb + (size_t)(r0+8)*LL + kb + cl) = make_float2(e10,e11);
                split2(e00,e01,pH[n][0],pL[n][0]);
                split2(e10,e11,pH[n][1],pL[n][1]);
            }
        }

        // ---- store next-V ----
        if (have_next){
            #pragma unroll
            for (int j=0;j<4;j++)
                split_store(kvn+VHI_O, kvn+VLO_O, ldoff + (uint32_t)(j*16*PSTR)*2u, vreg[j]);
        }

        // ---- O += P V, bf16x3 (P from registers, V via ldmatrix.trans) ----
        #pragma unroll
        for (int g=0;g<4;g++){
            uint32_t aPh[4] = {pH[2*g][0], pH[2*g][1], pH[2*g+1][0], pH[2*g+1][1]};
            uint32_t aPl[4] = {pL[2*g][0], pL[2*g][1], pL[2*g+1][0], pL[2*g+1][1]};
            #pragma unroll
            for (int p=0;p<4;p++){
                uint32_t vH[4], vL[4];
                ldsm4t(vH, kvb + VHI_O + vb_off[p] + g*2304);
                ldsm4t(vL, kvb + VLO_O + vb_off[p] + g*2304);
                #pragma unroll
                for (int nn=0;nn<2;nn++){
                    const int n = p*2+nn;
                    mma16816(ofr[n], aPh, &vH[nn*2]);
                    mma16816(ofr[n], aPh, &vL[nn*2]);
                    mma16816(ofr[n], aPl, &vH[nn*2]);
                }
            }
        }

        __syncthreads();   // buf consumed by all warps; buf^1 fully written
    }

    // ---- row-sum reduction -> inverse ----
    {
        float x0 = lp0, x1 = lp1;
        x0 += __shfl_xor_sync(0xffffffffu, x0, 1);
        x0 += __shfl_xor_sync(0xffffffffu, x0, 2);
        x1 += __shfl_xor_sync(0xffffffffu, x1, 1);
        x1 += __shfl_xor_sync(0xffffffffu, x1, 2);
        if ((l&3)==0){
            rowsum[r0]   = x0;
            rowsum[r0+8] = x1;
        }
    }
    __syncthreads();
    if (tid < TM){
        float s_ = rowsum[tid];
        float inv = s_>0.f ? 1.f/s_ : 0.f;
        g_inv[bh*LL + q0 + tid] = inv;
        rowsum[tid] = inv;
    }
    __syncthreads();

    // ---- normalized result write ----
    float* resb = res + ((size_t)bh*LL+q0)*DD;
    {
        float i0 = rowsum[r0], i1 = rowsum[r0+8];
        #pragma unroll
        for (int n=0;n<8;n++){
            const int dc = n*8 + (l&3)*2;
            *(float2*)(resb + (size_t)r0*DD + dc)     = make_float2(ofr[n][0]*i0, ofr[n][1]*i0);
            *(float2*)(resb + (size_t)(r0+8)*DD + dc) = make_float2(ofr[n][2]*i1, ofr[n][3]*i1);
        }
    }
}

// scale att_w rows by 1/l (att_w was written unnormalized)
__global__ __launch_bounds__(256) void fixup_kernel(float* __restrict__ attw)
{
    size_t idx = (size_t)blockIdx.x * blockDim.x + threadIdx.x;   // float4 index
    float inv = g_inv[idx >> 9];
    float4* p = (float4*)attw + idx;
    float4 val = *p;
    val.x *= inv; val.y *= inv; val.z *= inv; val.w *= inv;
    *p = val;
}

extern "C" void kernel_launch(void* const* d_in, const int* in_sizes, int n_in,
                              void* d_out, int out_size)
{
    const float* q     = (const float*)d_in[0];
    const float* k     = (const float*)d_in[1];
    const float* v     = (const float*)d_in[2];
    const int*   valid = (const int*)  d_in[3];
    const float* scale = (const float*)d_in[4];

    float* res  = (float*)d_out;                      // [B,H,L,D]
    float* attw = res + (size_t)NBH * LL * DD;        // [B,H,L,L]

    cudaFuncSetAttribute(attn_mma, cudaFuncAttributeMaxDynamicSharedMemorySize, SM_TOTAL);

    dim3 grid(LL / TM, NBH);   // (16, 32)
    attn_mma<<<grid, 256, SM_TOTAL>>>(q, k, v, valid, scale, res, attw);

    fixup_kernel<<<(NBH * (size_t)LL * LL / 4) / 256, 256>>>(attw);
}